// round 6
// baseline (speedup 1.0000x reference)
#include <cuda_runtime.h>
#include <cuda_bf16.h>
#include <math.h>

// Problem dims (fixed by reference setup_inputs)
constexpr int Bc = 32;
constexpr int Tc = 4;
constexpr int Lc = 196;
constexpr int Dc = 384;
constexpr int Hc = 1536;
constexpr int Mrows = Tc * Bc * Lc;   // 25088

// Scratch (device globals; allocation-free per harness rules)
__device__ float g_h1[(size_t)Mrows * Hc];   // pre-LN GEMM1 output  (~154 MB)
__device__ float g_s1[(size_t)Mrows * Hc];   // spikes layer 1       (~154 MB)
__device__ float g_h2[(size_t)Mrows * Dc];   // pre-LN GEMM2 output  (~38 MB)

// ---------------------------------------------------------------------------
// GEMM core: 128x128 tile, BK=8, 256 threads, 8x8 per thread (split 4+4,
// conflict-free), double-buffered, 1 sync/iter, 2 CTAs/SM.
// Bit-exactness contract: each output element is ONE fp32 FMA chain with k
// strictly ascending 0..K-1 (matches the reference einsum), bias added as a
// single separate __fadd_rn at the end.
// blockIdx.x = N-block (small), blockIdx.y = M-block  -> consecutive CTAs
// share the A block and the whole weight matrix through L2.
// Smem rows padded 128->132 floats (132 % 32 == 4) so the STS scatter
// (same column, different k) is conflict-free too.
// ---------------------------------------------------------------------------
#define GEMM_BODY(K_DIM, APTR_EXPR, BPTR_EXPR, BIAS, OUTBASE, OUT_LD)          \
    constexpr int BK = 8;                                                      \
    constexpr int LDS_ = 132;                                                  \
    __shared__ float As[2][BK][LDS_];                                          \
    __shared__ float Bs[2][BK][LDS_];                                          \
    const int tid = threadIdx.x;                                               \
    const int lr = tid >> 1;                                                   \
    const int lc = (tid & 1) * 4;                                              \
    const float* aptr = (APTR_EXPR);                                           \
    const float* bptr = (BPTR_EXPR);                                           \
    const int tx = tid & 15;                                                   \
    const int ty = tid >> 4;                                                   \
    float acc[8][8] = {};                                                      \
    float4 av = *(const float4*)aptr;                                          \
    float4 bv = *(const float4*)bptr;                                          \
    int buf = 0;                                                               \
    As[0][lc + 0][lr] = av.x; As[0][lc + 1][lr] = av.y;                        \
    As[0][lc + 2][lr] = av.z; As[0][lc + 3][lr] = av.w;                        \
    Bs[0][lc + 0][lr] = bv.x; Bs[0][lc + 1][lr] = bv.y;                        \
    Bs[0][lc + 2][lr] = bv.z; Bs[0][lc + 3][lr] = bv.w;                        \
    __syncthreads();                                                           \
    for (int k0 = BK; k0 < (K_DIM) + BK; k0 += BK) {                           \
        const bool more = (k0 < (K_DIM));                                      \
        if (more) {                                                            \
            av = *(const float4*)(aptr + k0);                                  \
            bv = *(const float4*)(bptr + k0);                                  \
        }                                                                      \
        _Pragma("unroll")                                                      \
        for (int k = 0; k < BK; k++) {                                         \
            const float4 a0 = *(const float4*)&As[buf][k][ty * 4];             \
            const float4 a1 = *(const float4*)&As[buf][k][64 + ty * 4];        \
            const float4 b0 = *(const float4*)&Bs[buf][k][tx * 4];             \
            const float4 b1 = *(const float4*)&Bs[buf][k][64 + tx * 4];        \
            const float am[8] = {a0.x, a0.y, a0.z, a0.w, a1.x, a1.y, a1.z, a1.w}; \
            const float bn[8] = {b0.x, b0.y, b0.z, b0.w, b1.x, b1.y, b1.z, b1.w}; \
            _Pragma("unroll")                                                  \
            for (int i = 0; i < 8; i++) {                                      \
                _Pragma("unroll")                                              \
                for (int j = 0; j < 8; j++)                                    \
                    acc[i][j] = __fmaf_rn(am[i], bn[j], acc[i][j]);            \
            }                                                                  \
        }                                                                      \
        if (more) {                                                            \
            buf ^= 1;                                                          \
            As[buf][lc + 0][lr] = av.x; As[buf][lc + 1][lr] = av.y;            \
            As[buf][lc + 2][lr] = av.z; As[buf][lc + 3][lr] = av.w;            \
            Bs[buf][lc + 0][lr] = bv.x; Bs[buf][lc + 1][lr] = bv.y;            \
            Bs[buf][lc + 2][lr] = bv.z; Bs[buf][lc + 3][lr] = bv.w;            \
            __syncthreads();                                                   \
        }                                                                      \
    }                                                                          \
    const int n_base = blockIdx.x * 128;                                       \
    const int m_base = blockIdx.y * 128;                                       \
    const float4 bb0 = *(const float4*)((BIAS) + n_base + tx * 4);             \
    const float4 bb1 = *(const float4*)((BIAS) + n_base + 64 + tx * 4);        \
    _Pragma("unroll")                                                          \
    for (int i = 0; i < 8; i++) {                                              \
        const int m = m_base + ((i < 4) ? (ty * 4 + i) : (64 + ty * 4 + i - 4)); \
        float* o = (OUTBASE) + (size_t)m * (OUT_LD) + n_base;                  \
        float4 o0, o1;                                                         \
        o0.x = __fadd_rn(acc[i][0], bb0.x); o0.y = __fadd_rn(acc[i][1], bb0.y);\
        o0.z = __fadd_rn(acc[i][2], bb0.z); o0.w = __fadd_rn(acc[i][3], bb0.w);\
        o1.x = __fadd_rn(acc[i][4], bb1.x); o1.y = __fadd_rn(acc[i][5], bb1.y);\
        o1.z = __fadd_rn(acc[i][6], bb1.z); o1.w = __fadd_rn(acc[i][7], bb1.w);\
        *(float4*)(o + tx * 4) = o0;                                           \
        *(float4*)(o + 64 + tx * 4) = o1;                                      \
    }

__global__ __launch_bounds__(256, 2) void gemm1_kernel(
    const float* __restrict__ x, const float* __restrict__ W1,
    const float* __restrict__ b1) {
    // A row r = (t*B + b)*L + l maps into x at ((b*T + t)*L + l)*D
    const int r_ = blockIdx.y * 128 + (threadIdx.x >> 1);
    const int l_  = r_ % Lc;
    const int tb_ = r_ / Lc;
    const int bI_ = tb_ % Bc;
    const int tI_ = tb_ / Bc;
    GEMM_BODY(Dc,
              x  + (size_t)((bI_ * Tc + tI_) * Lc + l_) * Dc + ((threadIdx.x & 1) * 4),
              W1 + (size_t)(blockIdx.x * 128 + (threadIdx.x >> 1)) * Dc + ((threadIdx.x & 1) * 4),
              b1, g_h1, Hc)
}

__global__ __launch_bounds__(256, 2) void gemm2_kernel(
    const float* __restrict__ W2, const float* __restrict__ b2) {
    GEMM_BODY(Hc,
              g_s1 + (size_t)(blockIdx.y * 128 + (threadIdx.x >> 1)) * Hc + ((threadIdx.x & 1) * 4),
              W2   + (size_t)(blockIdx.x * 128 + (threadIdx.x >> 1)) * Hc + ((threadIdx.x & 1) * 4),
              b2, g_h2, Dc)
}

// ---------------------------------------------------------------------------
// Fused LayerNorm + LIF, one warp per (b,l) row, looping over T with the
// membrane v resident in registers. Bit-exact op sequence:
//   mu   = f32( f64sum(y) / N )          (f64 reduce kills order noise)
//   var  = f32( f64sum( f32((y-mu)^2) ) / N )
//   rstd = 1.0f / sqrtf(var + 1e-5f)
//   yy   = ((y-mu)*rstd)*g + b
//   v    = v + (yy - v)*0.5f ; s = (v>=1) ; v *= (1-s)
// ---------------------------------------------------------------------------
template <int NC, bool TO_OUT>
__global__ __launch_bounds__(256) void ln_lif_kernel(
    const float* __restrict__ src, const float* __restrict__ gamma,
    const float* __restrict__ beta, float* __restrict__ dst) {
    constexpr int J = NC / 128;            // float4s per lane
    const int bl = blockIdx.x * 8 + (threadIdx.x >> 5);   // (b,l) index
    const int lane = threadIdx.x & 31;
    const int bI = bl / Lc, l = bl % Lc;

    float4 gg[J], bb[J];
#pragma unroll
    for (int j = 0; j < J; j++) {
        gg[j] = *(const float4*)(gamma + lane * 4 + j * 128);
        bb[j] = *(const float4*)(beta  + lane * 4 + j * 128);
    }
    float4 v[J];
#pragma unroll
    for (int j = 0; j < J; j++) v[j] = make_float4(0.f, 0.f, 0.f, 0.f);

    const int rbase = bI * Lc + l;
#pragma unroll
    for (int t = 0; t < Tc; t++) {
        const int r = t * (Bc * Lc) + rbase;
        const float* p = src + (size_t)r * NC;
        float4 y[J];
        double s = 0.0;
#pragma unroll
        for (int j = 0; j < J; j++) {
            y[j] = *(const float4*)(p + lane * 4 + j * 128);
            s += (double)y[j].x; s += (double)y[j].y;
            s += (double)y[j].z; s += (double)y[j].w;
        }
#pragma unroll
        for (int o = 16; o; o >>= 1) s += __shfl_xor_sync(0xffffffffu, s, o);
        const float mu = (float)(s / (double)NC);

        double s2 = 0.0;
#pragma unroll
        for (int j = 0; j < J; j++) {
            float d;
            d = __fsub_rn(y[j].x, mu); s2 += (double)__fmul_rn(d, d);
            d = __fsub_rn(y[j].y, mu); s2 += (double)__fmul_rn(d, d);
            d = __fsub_rn(y[j].z, mu); s2 += (double)__fmul_rn(d, d);
            d = __fsub_rn(y[j].w, mu); s2 += (double)__fmul_rn(d, d);
        }
#pragma unroll
        for (int o = 16; o; o >>= 1) s2 += __shfl_xor_sync(0xffffffffu, s2, o);
        const float var  = (float)(s2 / (double)NC);
        const float rs = __fdiv_rn(1.0f, __fsqrt_rn(__fadd_rn(var, 1e-5f)));

        float* q = TO_OUT
            ? dst + (size_t)((bI * Tc + t) * Lc + l) * NC
            : dst + (size_t)r * NC;
#pragma unroll
        for (int j = 0; j < J; j++) {
            float4 sp;
#define LIF_E(F)                                                               \
            {                                                                  \
                const float yy = __fadd_rn(                                    \
                    __fmul_rn(__fmul_rn(__fsub_rn(y[j].F, mu), rs), gg[j].F),  \
                    bb[j].F);                                                  \
                v[j].F = __fadd_rn(v[j].F,                                     \
                    __fmul_rn(__fsub_rn(yy, v[j].F), 0.5f));                   \
                sp.F = (v[j].F >= 1.0f) ? 1.f : 0.f;                           \
                v[j].F = __fmul_rn(v[j].F, __fsub_rn(1.0f, sp.F));             \
            }
            LIF_E(x) LIF_E(y) LIF_E(z) LIF_E(w)
#undef LIF_E
            *(float4*)(q + lane * 4 + j * 128) = sp;
        }
    }
}

// ---------------------------------------------------------------------------
extern "C" void kernel_launch(void* const* d_in, const int* in_sizes, int n_in,
                              void* d_out, int out_size) {
    const float* x   = (const float*)d_in[0];
    const float* W1  = (const float*)d_in[1];
    const float* b1  = (const float*)d_in[2];
    const float* g1  = (const float*)d_in[3];
    const float* be1 = (const float*)d_in[4];
    const float* W2  = (const float*)d_in[5];
    const float* b2  = (const float*)d_in[6];
    const float* g2  = (const float*)d_in[7];
    const float* be2 = (const float*)d_in[8];
    float* out = (float*)d_out;

    float *h1, *s1, *h2;
    cudaGetSymbolAddress((void**)&h1, g_h1);
    cudaGetSymbolAddress((void**)&s1, g_s1);
    cudaGetSymbolAddress((void**)&h2, g_h2);

    gemm1_kernel<<<dim3(Hc / 128, Mrows / 128), 256>>>(x, W1, b1);
    ln_lif_kernel<Hc, false><<<(Bc * Lc) / 8, 256>>>(h1, g1, be1, s1);
    gemm2_kernel<<<dim3(Dc / 128, Mrows / 128), 256>>>(W2, b2);
    ln_lif_kernel<Dc, true><<<(Bc * Lc) / 8, 256>>>(h2, g2, be2, out);
}